// round 13
// baseline (speedup 1.0000x reference)
#include <cuda_runtime.h>
#include <cuda_bf16.h>
#include <cstdint>

// RGINConv: out = feat + segment_sum_dst( feat[src] @ W[etype] )
// N=50000, E=640000, D=128, R=8.
//
// Tensor-core version: bf16-split (3-term) mma.sync.m16n8k16 GEMM.
//   feat = Fh + Fl (bf16 hi + bf16 residual), W = Wh + Wl.
//   X@W ~= Ah Bh + Al Bh + Ah Bl   (drops Al*Bl, ~2^-16 relative)
// Pipeline (graph-capturable, allocation-free):
//   1. copy_kernel   : out = feat
//   2. zero_kernel   : clear counters
//   3. hist_kernel   : per-relation histogram
//   4. offs_kernel   : prefix sums, reset cursors
//   5. scat_kernel   : counting-sort edge ids by relation -> g_order
//   6. wsplit/fsplit : bf16 hi/lo split of W and feat into scratch
//   7. gemm_tc_kernel: persistent work-stealing 128x128x128 tiles,
//                      cp.async double-buffered X, ldmatrix + mma.sync,
//                      scatter via red.global.add.v2.f32

#define D_FEAT   128
#define NUM_RELS 8
#define N_NODES_MAX 50000
#define MAX_E    640000
#define TILE_E   128
#define GT       256

__device__ int g_relcnt[NUM_RELS];
__device__ int g_relstart[NUM_RELS + 1];
__device__ int g_cursor[NUM_RELS];
__device__ int g_tilestart[NUM_RELS + 1];
__device__ int g_tilecur;
__device__ int g_order[MAX_E];

__device__ __nv_bfloat16 g_Fh[N_NODES_MAX * D_FEAT];
__device__ __nv_bfloat16 g_Fl[N_NODES_MAX * D_FEAT];
__device__ __nv_bfloat16 g_Wh[NUM_RELS * D_FEAT * D_FEAT];
__device__ __nv_bfloat16 g_Wl[NUM_RELS * D_FEAT * D_FEAT];

// ---------------------------------------------------------------- helpers
__device__ __forceinline__ void cp_async16(uint32_t sdst, const void* gsrc) {
    asm volatile("cp.async.cg.shared.global [%0], [%1], 16;" ::
                 "r"(sdst), "l"(gsrc));
}
__device__ __forceinline__ void cp_commit() {
    asm volatile("cp.async.commit_group;");
}
__device__ __forceinline__ void cp_wait1() {
    asm volatile("cp.async.wait_group 1;");
}
__device__ __forceinline__ void ldsm4(uint32_t* r, uint32_t a) {
    asm volatile("ldmatrix.sync.aligned.m8n8.x4.shared.b16 "
                 "{%0,%1,%2,%3}, [%4];"
                 : "=r"(r[0]), "=r"(r[1]), "=r"(r[2]), "=r"(r[3]) : "r"(a));
}
__device__ __forceinline__ void ldsm4t(uint32_t* r, uint32_t a) {
    asm volatile("ldmatrix.sync.aligned.m8n8.x4.trans.shared.b16 "
                 "{%0,%1,%2,%3}, [%4];"
                 : "=r"(r[0]), "=r"(r[1]), "=r"(r[2]), "=r"(r[3]) : "r"(a));
}
__device__ __forceinline__ void mma16816(float* c, const uint32_t* a,
                                         const uint32_t* b) {
    asm volatile("mma.sync.aligned.m16n8k16.row.col.f32.bf16.bf16.f32 "
                 "{%0,%1,%2,%3}, {%4,%5,%6,%7}, {%8,%9}, {%0,%1,%2,%3};"
                 : "+f"(c[0]), "+f"(c[1]), "+f"(c[2]), "+f"(c[3])
                 : "r"(a[0]), "r"(a[1]), "r"(a[2]), "r"(a[3]),
                   "r"(b[0]), "r"(b[1]));
}
// 256B bf16 rows, 16B chunks, XOR swizzle for conflict-free ldmatrix
__device__ __forceinline__ uint32_t swz(int row, int chunk) {
    return (uint32_t)(row * 256 + ((chunk ^ (row & 7)) << 4));
}

// ---------------------------------------------------------------- out = feat
__global__ void copy_kernel(const float4* __restrict__ feat4,
                            float4* __restrict__ out4, int n4) {
    int i = blockIdx.x * blockDim.x + threadIdx.x;
    if (i < n4) out4[i] = feat4[i];
}

__global__ void zero_kernel() {
    int t = threadIdx.x;
    if (t < NUM_RELS) g_relcnt[t] = 0;
    if (t == 0) g_tilecur = 0;
}

__global__ void hist_kernel(const int* __restrict__ et, int E) {
    __shared__ int h[NUM_RELS];
    if (threadIdx.x < NUM_RELS) h[threadIdx.x] = 0;
    __syncthreads();
    for (int i = blockIdx.x * blockDim.x + threadIdx.x; i < E;
         i += gridDim.x * blockDim.x)
        atomicAdd(&h[et[i]], 1);
    __syncthreads();
    if (threadIdx.x < NUM_RELS && h[threadIdx.x] > 0)
        atomicAdd(&g_relcnt[threadIdx.x], h[threadIdx.x]);
}

__global__ void offs_kernel() {
    if (threadIdx.x == 0 && blockIdx.x == 0) {
        int acc = 0, tacc = 0;
        for (int r = 0; r < NUM_RELS; r++) {
            g_relstart[r]  = acc;
            g_cursor[r]    = acc;
            g_tilestart[r] = tacc;
            acc  += g_relcnt[r];
            tacc += (g_relcnt[r] + TILE_E - 1) / TILE_E;
        }
        g_relstart[NUM_RELS]  = acc;
        g_tilestart[NUM_RELS] = tacc;
    }
}

__global__ void scat_kernel(const int* __restrict__ et, int E) {
    __shared__ int h[NUM_RELS];
    __shared__ int base[NUM_RELS];
    int t = threadIdx.x;
    if (t < NUM_RELS) h[t] = 0;
    __syncthreads();
    int e = blockIdx.x * blockDim.x + t;
    int myr = 0, loc = 0;
    if (e < E) {
        myr = et[e];
        loc = atomicAdd(&h[myr], 1);
    }
    __syncthreads();
    if (t < NUM_RELS && h[t] > 0) base[t] = atomicAdd(&g_cursor[t], h[t]);
    __syncthreads();
    if (e < E) g_order[base[myr] + loc] = e;
}

// ------------------------------------------------------- bf16 hi/lo splits
__global__ void wsplit_kernel(const float* __restrict__ W) {
    int i = blockIdx.x * blockDim.x + threadIdx.x;
    if (i < NUM_RELS * D_FEAT * D_FEAT) {
        float v = W[i];
        __nv_bfloat16 h = __float2bfloat16(v);
        g_Wh[i] = h;
        g_Wl[i] = __float2bfloat16(v - __bfloat162float(h));
    }
}
__global__ void fsplit_kernel(const float* __restrict__ feat, int n) {
    int i = blockIdx.x * blockDim.x + threadIdx.x;
    if (i < n) {
        float v = feat[i];
        __nv_bfloat16 h = __float2bfloat16(v);
        g_Fh[i] = h;
        g_Fl[i] = __float2bfloat16(v - __bfloat162float(h));
    }
}

// ----------------------------------------------------- tensor-core GEMM
// smem: sWh 32K | sWl 32K | sXh[2] 64K | sXl[2] 64K | sDst[2][128] | ctl
__global__ void __launch_bounds__(GT, 1)
gemm_tc_kernel(const int* __restrict__ src, const int* __restrict__ dst,
               float* __restrict__ out) {
    extern __shared__ char smem[];
    char* pWh = smem;                    // 32768
    char* pWl = pWh + 32768;             // 32768
    char* pXh = pWl + 32768;             // 2 * 32768
    char* pXl = pXh + 65536;             // 2 * 32768
    int*  sDst = (int*)(pXl + 65536);    // 2 * 128
    int*  sCtl = sDst + 2 * TILE_E;
    int*  sRS  = sCtl + 4;
    int*  sTS  = sRS + NUM_RELS + 1;

    const uint32_t uWh = (uint32_t)__cvta_generic_to_shared(pWh);
    const uint32_t uWl = (uint32_t)__cvta_generic_to_shared(pWl);
    const uint32_t uXh = (uint32_t)__cvta_generic_to_shared(pXh);
    const uint32_t uXl = (uint32_t)__cvta_generic_to_shared(pXl);

    const int tid  = threadIdx.x;
    const int lane = tid & 31;
    const int wid  = tid >> 5;
    const int warp_m = wid & 3;   // rows 32*warp_m
    const int warp_n = wid >> 2;  // cols 64*warp_n

    if (tid <= NUM_RELS) {
        sRS[tid] = g_relstart[tid];
        sTS[tid] = g_tilestart[tid];
    }
    __syncthreads();
    const int ntiles = sTS[NUM_RELS];

    auto relof = [&](int t) {
        int r = 0;
        while (sTS[r + 1] <= t) r++;
        return r;
    };
    // gather X rows (hi+lo) + dst ids for tile t into buffer b (cp.async)
    auto prefetch = [&](int t, int r, int b) {
        int tbeg = sRS[r] + (t - sTS[r]) * TILE_E;
        int ne   = min(TILE_E, sRS[r + 1] - tbeg);
        int row  = tid >> 1;       // 2 threads per row
        int half = tid & 1;        // chunks 0-7 / 8-15
        if (row < ne) {
            int e = g_order[tbeg + row];
            if (half == 0) sDst[b * TILE_E + row] = dst[e];
            size_t goff = (size_t)src[e] * D_FEAT + half * 64;
            const __nv_bfloat16* gh = g_Fh + goff;
            const __nv_bfloat16* gl = g_Fl + goff;
            #pragma unroll
            for (int j = 0; j < 8; j++) {
                int c = half * 8 + j;
                cp_async16(uXh + b * 32768 + swz(row, c), gh + j * 8);
                cp_async16(uXl + b * 32768 + swz(row, c), gl + j * 8);
            }
        }
    };
    auto load_W = [&](int r) {
        const __nv_bfloat16* wh = g_Wh + (size_t)r * D_FEAT * D_FEAT;
        const __nv_bfloat16* wl = g_Wl + (size_t)r * D_FEAT * D_FEAT;
        #pragma unroll
        for (int i = tid; i < D_FEAT * 16; i += GT) {   // 2048 chunks
            int row = i >> 4, c = i & 15;
            *(uint4*)(pWh + swz(row, c)) = *(const uint4*)(wh + row * 128 + c * 8);
            *(uint4*)(pWl + swz(row, c)) = *(const uint4*)(wl + row * 128 + c * 8);
        }
    };

    if (tid == 0) sCtl[0] = atomicAdd(&g_tilecur, 1);
    __syncthreads();
    int cur = sCtl[0];
    if (cur >= ntiles) return;
    int rcur = relof(cur);

    load_W(rcur);
    prefetch(cur, rcur, 0);
    cp_commit();

    int buf = 0;
    while (true) {
        if (tid == 0) sCtl[0] = atomicAdd(&g_tilecur, 1);
        __syncthreads();
        int nxt  = sCtl[0];
        int rnxt = -1;
        if (nxt < ntiles) {
            rnxt = relof(nxt);
            prefetch(nxt, rnxt, buf ^ 1);
        }
        cp_commit();
        cp_wait1();          // current buffer's group complete
        __syncthreads();     // all copies + any W reload visible

        int tbeg = sRS[rcur] + (cur - sTS[rcur]) * TILE_E;
        int ne   = min(TILE_E, sRS[rcur + 1] - tbeg);
        const uint32_t xh = uXh + buf * 32768;
        const uint32_t xl = uXl + buf * 32768;

        float acc[2][8][4];
        #pragma unroll
        for (int mt = 0; mt < 2; mt++)
            #pragma unroll
            for (int nt = 0; nt < 8; nt++)
                #pragma unroll
                for (int q = 0; q < 4; q++) acc[mt][nt][q] = 0.f;

        const int grp = lane >> 3, lr = lane & 7;
        #pragma unroll 1
        for (int ks = 0; ks < 8; ks++) {
            uint32_t Ah[2][4], Al[2][4], Bh[4][4], Bl[4][4];
            #pragma unroll
            for (int mt = 0; mt < 2; mt++) {
                int row = warp_m * 32 + mt * 16 + ((grp & 1) << 3) + lr;
                int c   = (ks << 1) + (grp >> 1);
                uint32_t off = swz(row, c);
                ldsm4(Ah[mt], xh + off);
                ldsm4(Al[mt], xl + off);
            }
            int krow = (ks << 4) + ((grp & 1) << 3) + lr;
            #pragma unroll
            for (int g = 0; g < 4; g++) {
                int c = warp_n * 8 + g * 2 + (grp >> 1);
                uint32_t off = swz(krow, c);
                ldsm4t(Bh[g], uWh + off);
                ldsm4t(Bl[g], uWl + off);
            }
            #pragma unroll
            for (int mt = 0; mt < 2; mt++)
                #pragma unroll
                for (int g = 0; g < 4; g++) {
                    mma16816(acc[mt][2 * g],     Ah[mt], &Bh[g][0]);
                    mma16816(acc[mt][2 * g + 1], Ah[mt], &Bh[g][2]);
                    mma16816(acc[mt][2 * g],     Al[mt], &Bh[g][0]);
                    mma16816(acc[mt][2 * g + 1], Al[mt], &Bh[g][2]);
                    mma16816(acc[mt][2 * g],     Ah[mt], &Bl[g][0]);
                    mma16816(acc[mt][2 * g + 1], Ah[mt], &Bl[g][2]);
                }
        }

        // scatter: D frag rows = warp_m*32 + mt*16 + h*8 + lane/4,
        //          cols = warp_n*64 + nt*8 + (lane%4)*2
        #pragma unroll
        for (int mt = 0; mt < 2; mt++)
            #pragma unroll
            for (int h = 0; h < 2; h++) {
                int rl = warp_m * 32 + mt * 16 + h * 8 + (lane >> 2);
                if (rl < ne) {
                    float* p = out + (size_t)sDst[buf * TILE_E + rl] * D_FEAT
                             + warp_n * 64 + (lane & 3) * 2;
                    #pragma unroll
                    for (int nt = 0; nt < 8; nt++) {
                        asm volatile(
                            "red.global.add.v2.f32 [%0], {%1,%2};" ::
                            "l"(p + nt * 8),
                            "f"(acc[mt][nt][h * 2]),
                            "f"(acc[mt][nt][h * 2 + 1]) : "memory");
                    }
                }
            }

        if (nxt >= ntiles) return;
        if (rnxt != rcur) {
            __syncthreads();   // readers done with old W
            load_W(rnxt);      // visible after next iteration's barrier
            rcur = rnxt;
        }
        cur = nxt;
        buf ^= 1;
    }
}

// =============================================================== entry point
extern "C" void kernel_launch(void* const* d_in, const int* in_sizes, int n_in,
                              void* d_out, int out_size) {
    const float* feat = (const float*)d_in[0];
    const float* W    = (const float*)d_in[1];
    const int*   et   = (const int*)d_in[2];
    const int*   src  = (const int*)d_in[3];
    const int*   dst  = (const int*)d_in[4];
    float*       out  = (float*)d_out;

    int E = in_sizes[2];
    if (E > MAX_E) E = MAX_E;
    int nfeat = in_sizes[0];
    if (nfeat > N_NODES_MAX * D_FEAT) nfeat = N_NODES_MAX * D_FEAT;

    // 1. out = feat
    {
        int n4 = out_size / 4;
        copy_kernel<<<(n4 + 255) / 256, 256>>>((const float4*)feat,
                                               (float4*)out, n4);
    }
    // 2-5. counting sort by relation
    zero_kernel<<<1, 32>>>();
    hist_kernel<<<256, 256>>>(et, E);
    offs_kernel<<<1, 1>>>();
    scat_kernel<<<(E + 255) / 256, 256>>>(et, E);

    // 6. bf16 hi/lo splits
    wsplit_kernel<<<(NUM_RELS * D_FEAT * D_FEAT + 255) / 256, 256>>>(W);
    fsplit_kernel<<<(nfeat + 255) / 256, 256>>>(feat, nfeat);

    // 7. persistent tensor-core grouped GEMM
    const int smem_bytes = 32768 * 2 + 65536 * 2 +
        (2 * TILE_E + 4 + 2 * (NUM_RELS + 1)) * (int)sizeof(int) + 64;
    cudaFuncSetAttribute(gemm_tc_kernel,
                         cudaFuncAttributeMaxDynamicSharedMemorySize,
                         smem_bytes);
    int nsm = 0;
    cudaDeviceGetAttribute(&nsm, cudaDevAttrMultiProcessorCount, 0);
    if (nsm < 148) nsm = 148;   // GB300: 152
    gemm_tc_kernel<<<nsm, GT, smem_bytes>>>(src, dst, out);
}

// round 15
// speedup vs baseline: 1.0510x; 1.0510x over previous
#include <cuda_runtime.h>
#include <cuda_bf16.h>
#include <cstdint>

// RGINConv: out = feat + segment_sum_dst( feat[src] @ W[etype] )
// N=50000, E=640000, D=128, R=8.
//
// Tensor-core version: bf16-split (3-term) mma.sync.m16n8k16 GEMM.
//   feat = Fh + Fl (bf16 hi + bf16 residual), W = Wh + Wl.
//   X@W ~= Ah Bh + Al Bh + Ah Bl   (drops Al*Bl, ~2^-16 relative)
// R13 measured: 327.7 us, rel_err 4.0e-6 (8-launch variant).
// R14: fuse copy+fsplit+zero into prep_kernel (one feat pass, -2 launches);
//      gemm moved to launch index 5 to catch the ncu -s 5 capture window.
// Pipeline (graph-capturable, allocation-free):
//   1. prep_kernel : out = feat; feat hi/lo bf16 split; zero counters
//   2. hist_kernel : per-relation histogram
//   3. offs_kernel : prefix sums, reset cursors
//   4. scat_kernel : counting-sort edge ids by relation -> g_order
//   5. wsplit_kernel: bf16 hi/lo split of W
//   6. gemm_tc_kernel: persistent work-stealing 128x128x128 tiles,
//      cp.async double-buffered X, ldmatrix + mma.sync, red.add.v2 scatter

#define D_FEAT   128
#define NUM_RELS 8
#define N_NODES_MAX 50000
#define MAX_E    640000
#define TILE_E   128
#define GT       256

__device__ int g_relcnt[NUM_RELS];
__device__ int g_relstart[NUM_RELS + 1];
__device__ int g_cursor[NUM_RELS];
__device__ int g_tilestart[NUM_RELS + 1];
__device__ int g_tilecur;
__device__ int g_order[MAX_E];

__device__ __nv_bfloat16 g_Fh[N_NODES_MAX * D_FEAT];
__device__ __nv_bfloat16 g_Fl[N_NODES_MAX * D_FEAT];
__device__ __nv_bfloat16 g_Wh[NUM_RELS * D_FEAT * D_FEAT];
__device__ __nv_bfloat16 g_Wl[NUM_RELS * D_FEAT * D_FEAT];

// ---------------------------------------------------------------- helpers
__device__ __forceinline__ void cp_async16(uint32_t sdst, const void* gsrc) {
    asm volatile("cp.async.cg.shared.global [%0], [%1], 16;" ::
                 "r"(sdst), "l"(gsrc));
}
__device__ __forceinline__ void cp_commit() {
    asm volatile("cp.async.commit_group;");
}
__device__ __forceinline__ void cp_wait1() {
    asm volatile("cp.async.wait_group 1;");
}
__device__ __forceinline__ void ldsm4(uint32_t* r, uint32_t a) {
    asm volatile("ldmatrix.sync.aligned.m8n8.x4.shared.b16 "
                 "{%0,%1,%2,%3}, [%4];"
                 : "=r"(r[0]), "=r"(r[1]), "=r"(r[2]), "=r"(r[3]) : "r"(a));
}
__device__ __forceinline__ void ldsm4t(uint32_t* r, uint32_t a) {
    asm volatile("ldmatrix.sync.aligned.m8n8.x4.trans.shared.b16 "
                 "{%0,%1,%2,%3}, [%4];"
                 : "=r"(r[0]), "=r"(r[1]), "=r"(r[2]), "=r"(r[3]) : "r"(a));
}
__device__ __forceinline__ void mma16816(float* c, const uint32_t* a,
                                         const uint32_t* b) {
    asm volatile("mma.sync.aligned.m16n8k16.row.col.f32.bf16.bf16.f32 "
                 "{%0,%1,%2,%3}, {%4,%5,%6,%7}, {%8,%9}, {%0,%1,%2,%3};"
                 : "+f"(c[0]), "+f"(c[1]), "+f"(c[2]), "+f"(c[3])
                 : "r"(a[0]), "r"(a[1]), "r"(a[2]), "r"(a[3]),
                   "r"(b[0]), "r"(b[1]));
}
// 256B bf16 rows, 16B chunks, XOR swizzle for conflict-free ldmatrix
__device__ __forceinline__ uint32_t swz(int row, int chunk) {
    return (uint32_t)(row * 256 + ((chunk ^ (row & 7)) << 4));
}

// --------------------------------------- prep: out=feat, split, zero ctrs
__global__ void prep_kernel(const float4* __restrict__ feat4,
                            float4* __restrict__ out4, int n4) {
    if (blockIdx.x == 0) {
        if (threadIdx.x < NUM_RELS) g_relcnt[threadIdx.x] = 0;
        if (threadIdx.x == 0) g_tilecur = 0;
    }
    int i = blockIdx.x * blockDim.x + threadIdx.x;
    if (i < n4) {
        float4 v = feat4[i];
        out4[i] = v;
        __nv_bfloat162 h0, h1, l0, l1;
        h0.x = __float2bfloat16(v.x);
        h0.y = __float2bfloat16(v.y);
        h1.x = __float2bfloat16(v.z);
        h1.y = __float2bfloat16(v.w);
        l0.x = __float2bfloat16(v.x - __bfloat162float(h0.x));
        l0.y = __float2bfloat16(v.y - __bfloat162float(h0.y));
        l1.x = __float2bfloat16(v.z - __bfloat162float(h1.x));
        l1.y = __float2bfloat16(v.w - __bfloat162float(h1.y));
        ((__nv_bfloat162*)g_Fh)[2 * i]     = h0;
        ((__nv_bfloat162*)g_Fh)[2 * i + 1] = h1;
        ((__nv_bfloat162*)g_Fl)[2 * i]     = l0;
        ((__nv_bfloat162*)g_Fl)[2 * i + 1] = l1;
    }
}

__global__ void hist_kernel(const int* __restrict__ et, int E) {
    __shared__ int h[NUM_RELS];
    if (threadIdx.x < NUM_RELS) h[threadIdx.x] = 0;
    __syncthreads();
    for (int i = blockIdx.x * blockDim.x + threadIdx.x; i < E;
         i += gridDim.x * blockDim.x)
        atomicAdd(&h[et[i]], 1);
    __syncthreads();
    if (threadIdx.x < NUM_RELS && h[threadIdx.x] > 0)
        atomicAdd(&g_relcnt[threadIdx.x], h[threadIdx.x]);
}

__global__ void offs_kernel() {
    if (threadIdx.x == 0 && blockIdx.x == 0) {
        int acc = 0, tacc = 0;
        for (int r = 0; r < NUM_RELS; r++) {
            g_relstart[r]  = acc;
            g_cursor[r]    = acc;
            g_tilestart[r] = tacc;
            acc  += g_relcnt[r];
            tacc += (g_relcnt[r] + TILE_E - 1) / TILE_E;
        }
        g_relstart[NUM_RELS]  = acc;
        g_tilestart[NUM_RELS] = tacc;
    }
}

__global__ void scat_kernel(const int* __restrict__ et, int E) {
    __shared__ int h[NUM_RELS];
    __shared__ int base[NUM_RELS];
    int t = threadIdx.x;
    if (t < NUM_RELS) h[t] = 0;
    __syncthreads();
    int e = blockIdx.x * blockDim.x + t;
    int myr = 0, loc = 0;
    if (e < E) {
        myr = et[e];
        loc = atomicAdd(&h[myr], 1);
    }
    __syncthreads();
    if (t < NUM_RELS && h[t] > 0) base[t] = atomicAdd(&g_cursor[t], h[t]);
    __syncthreads();
    if (e < E) g_order[base[myr] + loc] = e;
}

__global__ void wsplit_kernel(const float* __restrict__ W) {
    int i = blockIdx.x * blockDim.x + threadIdx.x;
    if (i < NUM_RELS * D_FEAT * D_FEAT) {
        float v = W[i];
        __nv_bfloat16 h = __float2bfloat16(v);
        g_Wh[i] = h;
        g_Wl[i] = __float2bfloat16(v - __bfloat162float(h));
    }
}

// ----------------------------------------------------- tensor-core GEMM
// smem: sWh 32K | sWl 32K | sXh[2] 64K | sXl[2] 64K | sDst[2][128] | ctl
__global__ void __launch_bounds__(GT, 1)
gemm_tc_kernel(const int* __restrict__ src, const int* __restrict__ dst,
               float* __restrict__ out) {
    extern __shared__ char smem[];
    char* pWh = smem;                    // 32768
    char* pWl = pWh + 32768;             // 32768
    char* pXh = pWl + 32768;             // 2 * 32768
    char* pXl = pXh + 65536;             // 2 * 32768
    int*  sDst = (int*)(pXl + 65536);    // 2 * 128
    int*  sCtl = sDst + 2 * TILE_E;
    int*  sRS  = sCtl + 4;
    int*  sTS  = sRS + NUM_RELS + 1;

    const uint32_t uWh = (uint32_t)__cvta_generic_to_shared(pWh);
    const uint32_t uWl = (uint32_t)__cvta_generic_to_shared(pWl);
    const uint32_t uXh = (uint32_t)__cvta_generic_to_shared(pXh);
    const uint32_t uXl = (uint32_t)__cvta_generic_to_shared(pXl);

    const int tid  = threadIdx.x;
    const int lane = tid & 31;
    const int wid  = tid >> 5;
    const int warp_m = wid & 3;   // rows 32*warp_m
    const int warp_n = wid >> 2;  // cols 64*warp_n

    if (tid <= NUM_RELS) {
        sRS[tid] = g_relstart[tid];
        sTS[tid] = g_tilestart[tid];
    }
    __syncthreads();
    const int ntiles = sTS[NUM_RELS];

    auto relof = [&](int t) {
        int r = 0;
        while (sTS[r + 1] <= t) r++;
        return r;
    };
    // gather X rows (hi+lo) + dst ids for tile t into buffer b (cp.async)
    auto prefetch = [&](int t, int r, int b) {
        int tbeg = sRS[r] + (t - sTS[r]) * TILE_E;
        int ne   = min(TILE_E, sRS[r + 1] - tbeg);
        int row  = tid >> 1;       // 2 threads per row
        int half = tid & 1;        // chunks 0-7 / 8-15
        if (row < ne) {
            int e = g_order[tbeg + row];
            if (half == 0) sDst[b * TILE_E + row] = dst[e];
            size_t goff = (size_t)src[e] * D_FEAT + half * 64;
            const __nv_bfloat16* gh = g_Fh + goff;
            const __nv_bfloat16* gl = g_Fl + goff;
            #pragma unroll
            for (int j = 0; j < 8; j++) {
                int c = half * 8 + j;
                cp_async16(uXh + b * 32768 + swz(row, c), gh + j * 8);
                cp_async16(uXl + b * 32768 + swz(row, c), gl + j * 8);
            }
        }
    };
    auto load_W = [&](int r) {
        const __nv_bfloat16* wh = g_Wh + (size_t)r * D_FEAT * D_FEAT;
        const __nv_bfloat16* wl = g_Wl + (size_t)r * D_FEAT * D_FEAT;
        #pragma unroll
        for (int i = tid; i < D_FEAT * 16; i += GT) {   // 2048 chunks
            int row = i >> 4, c = i & 15;
            *(uint4*)(pWh + swz(row, c)) = *(const uint4*)(wh + row * 128 + c * 8);
            *(uint4*)(pWl + swz(row, c)) = *(const uint4*)(wl + row * 128 + c * 8);
        }
    };

    if (tid == 0) sCtl[0] = atomicAdd(&g_tilecur, 1);
    __syncthreads();
    int cur = sCtl[0];
    if (cur >= ntiles) return;
    int rcur = relof(cur);

    load_W(rcur);
    prefetch(cur, rcur, 0);
    cp_commit();

    int buf = 0;
    while (true) {
        if (tid == 0) sCtl[0] = atomicAdd(&g_tilecur, 1);
        __syncthreads();
        int nxt  = sCtl[0];
        int rnxt = -1;
        if (nxt < ntiles) {
            rnxt = relof(nxt);
            prefetch(nxt, rnxt, buf ^ 1);
        }
        cp_commit();
        cp_wait1();          // current buffer's group complete
        __syncthreads();     // all copies + any W reload visible

        int tbeg = sRS[rcur] + (cur - sTS[rcur]) * TILE_E;
        int ne   = min(TILE_E, sRS[rcur + 1] - tbeg);
        const uint32_t xh = uXh + buf * 32768;
        const uint32_t xl = uXl + buf * 32768;

        float acc[2][8][4];
        #pragma unroll
        for (int mt = 0; mt < 2; mt++)
            #pragma unroll
            for (int nt = 0; nt < 8; nt++)
                #pragma unroll
                for (int q = 0; q < 4; q++) acc[mt][nt][q] = 0.f;

        const int grp = lane >> 3, lr = lane & 7;
        #pragma unroll 1
        for (int ks = 0; ks < 8; ks++) {
            uint32_t Ah[2][4], Al[2][4], Bh[4][4], Bl[4][4];
            #pragma unroll
            for (int mt = 0; mt < 2; mt++) {
                int row = warp_m * 32 + mt * 16 + ((grp & 1) << 3) + lr;
                int c   = (ks << 1) + (grp >> 1);
                uint32_t off = swz(row, c);
                ldsm4(Ah[mt], xh + off);
                ldsm4(Al[mt], xl + off);
            }
            int krow = (ks << 4) + ((grp & 1) << 3) + lr;
            #pragma unroll
            for (int g = 0; g < 4; g++) {
                int c = warp_n * 8 + g * 2 + (grp >> 1);
                uint32_t off = swz(krow, c);
                ldsm4t(Bh[g], uWh + off);
                ldsm4t(Bl[g], uWl + off);
            }
            #pragma unroll
            for (int mt = 0; mt < 2; mt++)
                #pragma unroll
                for (int g = 0; g < 4; g++) {
                    mma16816(acc[mt][2 * g],     Ah[mt], &Bh[g][0]);
                    mma16816(acc[mt][2 * g + 1], Ah[mt], &Bh[g][2]);
                    mma16816(acc[mt][2 * g],     Al[mt], &Bh[g][0]);
                    mma16816(acc[mt][2 * g + 1], Al[mt], &Bh[g][2]);
                    mma16816(acc[mt][2 * g],     Ah[mt], &Bl[g][0]);
                    mma16816(acc[mt][2 * g + 1], Ah[mt], &Bl[g][2]);
                }
        }

        // scatter: D frag rows = warp_m*32 + mt*16 + h*8 + lane/4,
        //          cols = warp_n*64 + nt*8 + (lane%4)*2
        #pragma unroll
        for (int mt = 0; mt < 2; mt++)
            #pragma unroll
            for (int h = 0; h < 2; h++) {
                int rl = warp_m * 32 + mt * 16 + h * 8 + (lane >> 2);
                if (rl < ne) {
                    float* p = out + (size_t)sDst[buf * TILE_E + rl] * D_FEAT
                             + warp_n * 64 + (lane & 3) * 2;
                    #pragma unroll
                    for (int nt = 0; nt < 8; nt++) {
                        asm volatile(
                            "red.global.add.v2.f32 [%0], {%1,%2};" ::
                            "l"(p + nt * 8),
                            "f"(acc[mt][nt][h * 2]),
                            "f"(acc[mt][nt][h * 2 + 1]) : "memory");
                    }
                }
            }

        if (nxt >= ntiles) return;
        if (rnxt != rcur) {
            __syncthreads();   // readers done with old W
            load_W(rnxt);      // visible after next iteration's barrier
            rcur = rnxt;
        }
        cur = nxt;
        buf ^= 1;
    }
}

// =============================================================== entry point
extern "C" void kernel_launch(void* const* d_in, const int* in_sizes, int n_in,
                              void* d_out, int out_size) {
    const float* feat = (const float*)d_in[0];
    const float* W    = (const float*)d_in[1];
    const int*   et   = (const int*)d_in[2];
    const int*   src  = (const int*)d_in[3];
    const int*   dst  = (const int*)d_in[4];
    float*       out  = (float*)d_out;

    int E = in_sizes[2];
    if (E > MAX_E) E = MAX_E;
    int nfeat = in_sizes[0];
    if (nfeat > N_NODES_MAX * D_FEAT) nfeat = N_NODES_MAX * D_FEAT;

    // 1. out = feat; feat hi/lo split; zero counters   (one feat pass)
    {
        int n4 = nfeat / 4;
        prep_kernel<<<(n4 + 255) / 256, 256>>>((const float4*)feat,
                                               (float4*)out, n4);
    }
    // 2-4. counting sort by relation
    hist_kernel<<<256, 256>>>(et, E);
    offs_kernel<<<1, 1>>>();
    scat_kernel<<<(E + 255) / 256, 256>>>(et, E);

    // 5. W hi/lo split
    wsplit_kernel<<<(NUM_RELS * D_FEAT * D_FEAT + 255) / 256, 256>>>(W);

    // 6. persistent tensor-core grouped GEMM (launch index 5 for ncu -s 5)
    const int smem_bytes = 32768 * 2 + 65536 * 2 +
        (2 * TILE_E + 4 + 2 * (NUM_RELS + 1)) * (int)sizeof(int) + 64;
    cudaFuncSetAttribute(gemm_tc_kernel,
                         cudaFuncAttributeMaxDynamicSharedMemorySize,
                         smem_bytes);
    int nsm = 0;
    cudaDeviceGetAttribute(&nsm, cudaDevAttrMultiProcessorCount, 0);
    if (nsm < 148) nsm = 148;   // GB300: 152
    gemm_tc_kernel<<<nsm, GT, smem_bytes>>>(src, dst, out);
}